// round 9
// baseline (speedup 1.0000x reference)
#include <cuda_runtime.h>
#include <cuda_bf16.h>

#define NN 50000
#define NE 800000
#define DH 64
#define NG 128
#define NC 10

#define SCAN_BS 512
#define SCAN_NB ((NN + SCAN_BS - 1) / SCAN_BS)   // 98

#define XT_STRIDE 68   // floats per XsT row; 17x16B units, 17 mod 8 = 1 -> conflict-free f4 reads

// ---------------- scratch (static device globals; no allocation) ----------------
__device__ __align__(16) float g_dinv[NN];          // deg -> rsqrt(deg), in place
__device__ int   g_rowcnt[NN];                      // histogram of dst
__device__ int   g_rowptr[NN + 1];                  // CSR row offsets
__device__ int   g_cursor[NN];                      // scatter cursors
__device__ int   g_bsum[SCAN_NB];                   // scan block sums
__device__ int   g_gstart[NG + 1];                  // graph node-range starts
__device__ __align__(16) int2  g_epack[NE];         // {src, norm-as-int} sorted by dst
__device__ __align__(16) float g_xw[NN * DH];       // GEMM output (per layer)
__device__ __align__(16) float g_hA[NN * DH];       // aggregation ping
__device__ __align__(16) float g_hB[NN * DH];       // aggregation pong

__device__ __forceinline__ float* selbuf(int s) {
    return (s == 1) ? g_hA : g_hB;   // s in {1,2}
}

// ---------------- degree precompute ----------------
__global__ void k_init_deg() {
    int n = blockIdx.x * blockDim.x + threadIdx.x;
    if (n < NN) { g_dinv[n] = 1.0f; g_rowcnt[n] = 0; }
}

__global__ void k_deg_hist(const int* __restrict__ dst,
                           const float* __restrict__ ew) {
    int e = blockIdx.x * blockDim.x + threadIdx.x;
    if (e < NE) {
        int d = dst[e];
        atomicAdd(&g_dinv[d], ew[e]);
        atomicAdd(&g_rowcnt[d], 1);
    }
}

// ---------------- 3-phase parallel exclusive scan of rowcnt ----------------
__global__ void __launch_bounds__(SCAN_BS) k_scan_local() {
    __shared__ int sh[SCAN_BS];
    int t = threadIdx.x;
    int idx = blockIdx.x * SCAN_BS + t;
    int val = (idx < NN) ? g_rowcnt[idx] : 0;
    sh[t] = val;
    __syncthreads();
#pragma unroll
    for (int off = 1; off < SCAN_BS; off <<= 1) {
        int v = sh[t];
        if (t >= off) v += sh[t - off];
        __syncthreads();
        sh[t] = v;
        __syncthreads();
    }
    if (idx < NN) g_rowptr[idx] = sh[t] - val;
    if (t == SCAN_BS - 1) g_bsum[blockIdx.x] = sh[t];
}

__global__ void __launch_bounds__(128) k_scan_block() {
    __shared__ int sh[128];
    int t = threadIdx.x;
    int val = (t < SCAN_NB) ? g_bsum[t] : 0;
    sh[t] = val;
    __syncthreads();
#pragma unroll
    for (int off = 1; off < 128; off <<= 1) {
        int v = sh[t];
        if (t >= off) v += sh[t - off];
        __syncthreads();
        sh[t] = v;
        __syncthreads();
    }
    if (t < SCAN_NB) g_bsum[t] = sh[t] - val;
}

// phase 3: add block offsets, init cursor, fused rsqrt(deg) and graph bounds
__global__ void k_scan_add_rsqrt(const int* __restrict__ batch) {
    int idx = blockIdx.x * blockDim.x + threadIdx.x;
    if (idx < NN) {
        int v = g_rowptr[idx] + g_bsum[idx / SCAN_BS];
        g_rowptr[idx] = v;
        g_cursor[idx] = v;
        float d = g_dinv[idx];
        g_dinv[idx] = (d > 0.0f) ? rsqrtf(d) : 0.0f;

        int b0 = batch[idx];
        int b1 = (idx + 1 < NN) ? batch[idx + 1] : NG;
        for (int g = b0 + 1; g <= b1; g++) g_gstart[g] = idx + 1;
        if (idx == 0) {
            for (int g = 0; g <= b0; g++) g_gstart[g] = 0;
        }
    }
    if (idx == 0) g_rowptr[NN] = NE;
}

// ---------------- scatter edges into CSR order, fusing norm computation ----------
__global__ void k_scatter(const int* __restrict__ src,
                          const int* __restrict__ dst,
                          const float* __restrict__ ew) {
    int e = blockIdx.x * blockDim.x + threadIdx.x;
    if (e < NE) {
        int s = src[e], d = dst[e];
        int pos = atomicAdd(&g_cursor[d], 1);
        float nm = g_dinv[s] * ew[e] * g_dinv[d];
        g_epack[pos] = make_int2(s, __float_as_int(nm));
    }
}

// ---------------- dense GEMM: xw = relu?(xin) @ W, [NN,64]@[64,64] ----------------
// 128 threads/block, 64-node tile, 4 nodes x 8 cols per thread.
// Smaller block -> ~6 blocks/SM (24 warps) for latency hiding of the LDS chain.
__global__ void __launch_bounds__(128) k_gemm(int in_sel,
                                              const float* __restrict__ ext,
                                              const float* __restrict__ W,
                                              int relu) {
    __shared__ float4 Ws4[DH * 16];              // W[k][0..63], 16 float4 per k
    __shared__ float XsT[DH * XT_STRIDE];        // XsT[k][node], 64 nodes + pad

    const float* xin = (in_sel == 1) ? g_hA : (in_sel == 2) ? g_hB : ext;
    const int tid = threadIdx.x;
    const int r = tid >> 3;      // 0..15 : node group (4 nodes each)
    const int c = tid & 7;       // 0..7  : col group (8 cols each)
    const int node0 = blockIdx.x * 64;

    const float4* W4 = (const float4*)W;
    for (int i = tid; i < DH * 16; i += 128) Ws4[i] = W4[i];

    // fill XsT[k][n] = relu?(xin[node0+n][k]); lane varies k -> coalesced gmem read
    for (int i = tid; i < 64 * DH; i += 128) {
        int n = i >> 6, k = i & 63;
        int nn = node0 + n;
        float v = (nn < NN) ? xin[nn * DH + k] : 0.0f;
        if (relu) v = fmaxf(v, 0.0f);
        XsT[k * XT_STRIDE + n] = v;
    }
    __syncthreads();

    float4 acc[8];
#pragma unroll
    for (int j = 0; j < 8; j++) acc[j] = make_float4(0.f, 0.f, 0.f, 0.f);

#pragma unroll 4
    for (int k = 0; k < DH; k++) {
        float4 xv = *(const float4*)&XsT[k * XT_STRIDE + r * 4];   // 4 node values
        float4 w0 = Ws4[k * 16 + c * 2];                           // cols c*8..c*8+3
        float4 w1 = Ws4[k * 16 + c * 2 + 1];                       // cols c*8+4..+7
        acc[0].x = fmaf(xv.x, w0.x, acc[0].x); acc[0].y = fmaf(xv.x, w0.y, acc[0].y);
        acc[0].z = fmaf(xv.x, w0.z, acc[0].z); acc[0].w = fmaf(xv.x, w0.w, acc[0].w);
        acc[1].x = fmaf(xv.x, w1.x, acc[1].x); acc[1].y = fmaf(xv.x, w1.y, acc[1].y);
        acc[1].z = fmaf(xv.x, w1.z, acc[1].z); acc[1].w = fmaf(xv.x, w1.w, acc[1].w);
        acc[2].x = fmaf(xv.y, w0.x, acc[2].x); acc[2].y = fmaf(xv.y, w0.y, acc[2].y);
        acc[2].z = fmaf(xv.y, w0.z, acc[2].z); acc[2].w = fmaf(xv.y, w0.w, acc[2].w);
        acc[3].x = fmaf(xv.y, w1.x, acc[3].x); acc[3].y = fmaf(xv.y, w1.y, acc[3].y);
        acc[3].z = fmaf(xv.y, w1.z, acc[3].z); acc[3].w = fmaf(xv.y, w1.w, acc[3].w);
        acc[4].x = fmaf(xv.z, w0.x, acc[4].x); acc[4].y = fmaf(xv.z, w0.y, acc[4].y);
        acc[4].z = fmaf(xv.z, w0.z, acc[4].z); acc[4].w = fmaf(xv.z, w0.w, acc[4].w);
        acc[5].x = fmaf(xv.z, w1.x, acc[5].x); acc[5].y = fmaf(xv.z, w1.y, acc[5].y);
        acc[5].z = fmaf(xv.z, w1.z, acc[5].z); acc[5].w = fmaf(xv.z, w1.w, acc[5].w);
        acc[6].x = fmaf(xv.w, w0.x, acc[6].x); acc[6].y = fmaf(xv.w, w0.y, acc[6].y);
        acc[6].z = fmaf(xv.w, w0.z, acc[6].z); acc[6].w = fmaf(xv.w, w0.w, acc[6].w);
        acc[7].x = fmaf(xv.w, w1.x, acc[7].x); acc[7].y = fmaf(xv.w, w1.y, acc[7].y);
        acc[7].z = fmaf(xv.w, w1.z, acc[7].z); acc[7].w = fmaf(xv.w, w1.w, acc[7].w);
    }

#pragma unroll
    for (int i = 0; i < 4; i++) {
        int n = node0 + r * 4 + i;
        if (n < NN) {
            float4* o = (float4*)(g_xw + n * DH + c * 8);
            o[0] = acc[i * 2];
            o[1] = acc[i * 2 + 1];
        }
    }
}

// ---------------- pull aggregation: warp per node, 8-deep MLP, no atomics --------
__global__ void __launch_bounds__(256) k_agg(int out_sel, const float* __restrict__ b) {
    int warp = (blockIdx.x * blockDim.x + threadIdx.x) >> 5;
    int lane = threadIdx.x & 31;
    if (warp >= NN) return;
    int n = warp;

    const float2* xw2 = (const float2*)g_xw;
    const float2* b2v = (const float2*)b;

    float di = g_dinv[n];
    float sl = di * di;
    float2 self = xw2[n * 32 + lane];
    float2 bb = b2v[lane];
    float acc0 = fmaf(self.x, sl, bb.x);
    float acc1 = fmaf(self.y, sl, bb.y);

    int beg = g_rowptr[n];
    int end = g_rowptr[n + 1];

    int i = beg;
    for (; i + 8 <= end; i += 8) {
        int2 p0 = g_epack[i];
        int2 p1 = g_epack[i + 1];
        int2 p2 = g_epack[i + 2];
        int2 p3 = g_epack[i + 3];
        int2 p4 = g_epack[i + 4];
        int2 p5 = g_epack[i + 5];
        int2 p6 = g_epack[i + 6];
        int2 p7 = g_epack[i + 7];
        float2 f0 = xw2[p0.x * 32 + lane];
        float2 f1 = xw2[p1.x * 32 + lane];
        float2 f2 = xw2[p2.x * 32 + lane];
        float2 f3 = xw2[p3.x * 32 + lane];
        float2 f4 = xw2[p4.x * 32 + lane];
        float2 f5 = xw2[p5.x * 32 + lane];
        float2 f6 = xw2[p6.x * 32 + lane];
        float2 f7 = xw2[p7.x * 32 + lane];
        acc0 = fmaf(__int_as_float(p0.y), f0.x, acc0);  acc1 = fmaf(__int_as_float(p0.y), f0.y, acc1);
        acc0 = fmaf(__int_as_float(p1.y), f1.x, acc0);  acc1 = fmaf(__int_as_float(p1.y), f1.y, acc1);
        acc0 = fmaf(__int_as_float(p2.y), f2.x, acc0);  acc1 = fmaf(__int_as_float(p2.y), f2.y, acc1);
        acc0 = fmaf(__int_as_float(p3.y), f3.x, acc0);  acc1 = fmaf(__int_as_float(p3.y), f3.y, acc1);
        acc0 = fmaf(__int_as_float(p4.y), f4.x, acc0);  acc1 = fmaf(__int_as_float(p4.y), f4.y, acc1);
        acc0 = fmaf(__int_as_float(p5.y), f5.x, acc0);  acc1 = fmaf(__int_as_float(p5.y), f5.y, acc1);
        acc0 = fmaf(__int_as_float(p6.y), f6.x, acc0);  acc1 = fmaf(__int_as_float(p6.y), f6.y, acc1);
        acc0 = fmaf(__int_as_float(p7.y), f7.x, acc0);  acc1 = fmaf(__int_as_float(p7.y), f7.y, acc1);
    }
    for (; i + 2 <= end; i += 2) {
        int2 p0 = g_epack[i];
        int2 p1 = g_epack[i + 1];
        float2 f0 = xw2[p0.x * 32 + lane];
        float2 f1 = xw2[p1.x * 32 + lane];
        acc0 = fmaf(__int_as_float(p0.y), f0.x, acc0);  acc1 = fmaf(__int_as_float(p0.y), f0.y, acc1);
        acc0 = fmaf(__int_as_float(p1.y), f1.x, acc0);  acc1 = fmaf(__int_as_float(p1.y), f1.y, acc1);
    }
    if (i < end) {
        int2 p = g_epack[i];
        float2 f = xw2[p.x * 32 + lane];
        acc0 = fmaf(__int_as_float(p.y), f.x, acc0);
        acc1 = fmaf(__int_as_float(p.y), f.y, acc1);
    }

    float2* out2 = (float2*)selbuf(out_sel);
    out2[n * 32 + lane] = make_float2(acc0, acc1);
}

// ---------------- fused segmented mean pool + linear head ----------------
__global__ void __launch_bounds__(256) k_pool_head(int h_sel,
                                                   const float* __restrict__ Wl,
                                                   const float* __restrict__ bl,
                                                   float* __restrict__ out) {
    __shared__ float sh[4][DH];
    __shared__ float pooled[DH];
    int g = blockIdx.x;
    int w = threadIdx.x >> 6;
    int c = threadIdx.x & 63;
    int lo = g_gstart[g], hi = g_gstart[g + 1];
    const float* h = selbuf(h_sel);

    float acc = 0.0f;
    for (int n = lo + w; n < hi; n += 4)
        acc += h[n * DH + c];
    sh[w][c] = acc;
    __syncthreads();
    if (w == 0) {
        float s = sh[0][c] + sh[1][c] + sh[2][c] + sh[3][c];
        float cnt = (float)(hi - lo);
        pooled[c] = s / fmaxf(cnt, 1.0f);
    }
    __syncthreads();
    int t = threadIdx.x;
    if (t < NC) {
        float a = bl[t];
#pragma unroll
        for (int hh = 0; hh < DH; hh++) a = fmaf(pooled[hh], Wl[hh * NC + t], a);
        out[g * NC + t] = a;
    }
}

// ---------------- host launch ----------------
extern "C" void kernel_launch(void* const* d_in, const int* in_sizes, int n_in,
                              void* d_out, int out_size) {
    const float* x       = (const float*)d_in[0];
    const int*   ei      = (const int*)d_in[1];   // int32 (JAX x64 disabled)
    const int*   src     = ei;
    const int*   dst     = ei + NE;
    const int*   batch   = (const int*)d_in[2];   // int32, sorted
    const float* ew      = (const float*)d_in[3];
    const float* W1 = (const float*)d_in[4];
    const float* b1 = (const float*)d_in[5];
    const float* W2 = (const float*)d_in[6];
    const float* b2 = (const float*)d_in[7];
    const float* W3 = (const float*)d_in[8];
    const float* b3 = (const float*)d_in[9];
    const float* Wl = (const float*)d_in[10];
    const float* bl = (const float*)d_in[11];
    float* out = (float*)d_out;

    const int TB = 256;
    const int gN   = (NN + TB - 1) / TB;
    const int gE   = (NE + TB - 1) / TB;
    const int gAgg = (NN * 32 + TB - 1) / TB;     // warp per node
    const int gGemm = (NN + 63) / 64;             // 64 nodes per block

    // launches 1-3: start of CSR precompute
    k_init_deg<<<gN, TB>>>();
    k_deg_hist<<<gE, TB>>>(dst, ew);
    k_scan_local<<<SCAN_NB, SCAN_BS>>>();
    // launch 4: gemm layer 1 (independent of CSR chain) -- profiled by ncu
    k_gemm<<<gGemm, 128>>>(0, x, W1, 0);
    // finish CSR precompute
    k_scan_block<<<1, 128>>>();
    k_scan_add_rsqrt<<<gN, TB>>>(batch);
    k_scatter<<<gE, TB>>>(src, dst, ew);

    // layer 1 aggregation -> hA   (relu deferred to layer 2 read)
    k_agg<<<gAgg, TB>>>(1, b1);

    // layer 2: relu(hA) @ W2 -> agg -> hB
    k_gemm<<<gGemm, 128>>>(1, nullptr, W2, 1);
    k_agg<<<gAgg, TB>>>(2, b2);

    // layer 3: relu(hB) @ W3 -> agg -> hA (= h3, no relu)
    k_gemm<<<gGemm, 128>>>(2, nullptr, W3, 1);
    k_agg<<<gAgg, TB>>>(1, b3);

    // fused global mean pool + linear head
    k_pool_head<<<NG, TB>>>(1, Wl, bl, out);
}

// round 10
// speedup vs baseline: 1.0388x; 1.0388x over previous
#include <cuda_runtime.h>
#include <cuda_bf16.h>

#define NN 50000
#define NE 800000
#define DH 64
#define NG 128
#define NC 10

#define SCAN_BS 512
#define SCAN_NB ((NN + SCAN_BS - 1) / SCAN_BS)   // 98

#define XT_STRIDE 132   // floats per XsT row (128 nodes + pad), float4-aligned

// ---------------- scratch (static device globals; no allocation) ----------------
__device__ __align__(16) float g_dinv[NN];
__device__ int   g_rowcnt[NN];
__device__ int   g_rowptr[NN + 1];
__device__ int   g_cursor[NN];
__device__ int   g_bsum[SCAN_NB];
__device__ int   g_gstart[NG + 1];
__device__ __align__(16) int2  g_epack[NE];         // {src, norm-as-int} sorted by dst
__device__ __align__(16) float g_xw[NN * DH];
__device__ __align__(16) float g_hA[NN * DH];
__device__ __align__(16) float g_hB[NN * DH];

__device__ __forceinline__ float* selbuf(int s) {
    return (s == 1) ? g_hA : g_hB;
}

// ---------------- degree precompute ----------------
__global__ void k_init_deg() {
    int n = blockIdx.x * blockDim.x + threadIdx.x;
    if (n < NN) { g_dinv[n] = 1.0f; g_rowcnt[n] = 0; }
}

__global__ void k_deg_hist(const int* __restrict__ dst,
                           const float* __restrict__ ew) {
    int e = blockIdx.x * blockDim.x + threadIdx.x;
    if (e < NE) {
        int d = dst[e];
        atomicAdd(&g_dinv[d], ew[e]);
        atomicAdd(&g_rowcnt[d], 1);
    }
}

// ---------------- 3-phase parallel exclusive scan of rowcnt ----------------
__global__ void __launch_bounds__(SCAN_BS) k_scan_local() {
    __shared__ int sh[SCAN_BS];
    int t = threadIdx.x;
    int idx = blockIdx.x * SCAN_BS + t;
    int val = (idx < NN) ? g_rowcnt[idx] : 0;
    sh[t] = val;
    __syncthreads();
#pragma unroll
    for (int off = 1; off < SCAN_BS; off <<= 1) {
        int v = sh[t];
        if (t >= off) v += sh[t - off];
        __syncthreads();
        sh[t] = v;
        __syncthreads();
    }
    if (idx < NN) g_rowptr[idx] = sh[t] - val;
    if (t == SCAN_BS - 1) g_bsum[blockIdx.x] = sh[t];
}

__global__ void __launch_bounds__(128) k_scan_block() {
    __shared__ int sh[128];
    int t = threadIdx.x;
    int val = (t < SCAN_NB) ? g_bsum[t] : 0;
    sh[t] = val;
    __syncthreads();
#pragma unroll
    for (int off = 1; off < 128; off <<= 1) {
        int v = sh[t];
        if (t >= off) v += sh[t - off];
        __syncthreads();
        sh[t] = v;
        __syncthreads();
    }
    if (t < SCAN_NB) g_bsum[t] = sh[t] - val;
}

// phase 3: add block offsets, init cursor, fused rsqrt(deg) and graph bounds
__global__ void k_scan_add_rsqrt(const int* __restrict__ batch) {
    int idx = blockIdx.x * blockDim.x + threadIdx.x;
    if (idx < NN) {
        int v = g_rowptr[idx] + g_bsum[idx / SCAN_BS];
        g_rowptr[idx] = v;
        g_cursor[idx] = v;
        float d = g_dinv[idx];
        g_dinv[idx] = (d > 0.0f) ? rsqrtf(d) : 0.0f;

        int b0 = batch[idx];
        int b1 = (idx + 1 < NN) ? batch[idx + 1] : NG;
        for (int g = b0 + 1; g <= b1; g++) g_gstart[g] = idx + 1;
        if (idx == 0) {
            for (int g = 0; g <= b0; g++) g_gstart[g] = 0;
        }
    }
    if (idx == 0) g_rowptr[NN] = NE;
}

// ---------------- scatter edges into CSR order, fusing norm computation ----------
__global__ void k_scatter(const int* __restrict__ src,
                          const int* __restrict__ dst,
                          const float* __restrict__ ew) {
    int e = blockIdx.x * blockDim.x + threadIdx.x;
    if (e < NE) {
        int s = src[e], d = dst[e];
        int pos = atomicAdd(&g_cursor[d], 1);
        float nm = g_dinv[s] * ew[e] * g_dinv[d];
        g_epack[pos] = make_int2(s, __float_as_int(nm));
    }
}

// ---------------- dense GEMM: 8 nodes x 8 cols per thread, sw-pipelined ----------
__device__ __forceinline__ void fma8x8(float4* acc, float4 xa0, float4 xa1,
                                       float4 w0, float4 w1) {
    float xn[8] = {xa0.x, xa0.y, xa0.z, xa0.w, xa1.x, xa1.y, xa1.z, xa1.w};
#pragma unroll
    for (int i = 0; i < 8; i++) {
        acc[2 * i].x     = fmaf(xn[i], w0.x, acc[2 * i].x);
        acc[2 * i].y     = fmaf(xn[i], w0.y, acc[2 * i].y);
        acc[2 * i].z     = fmaf(xn[i], w0.z, acc[2 * i].z);
        acc[2 * i].w     = fmaf(xn[i], w0.w, acc[2 * i].w);
        acc[2 * i + 1].x = fmaf(xn[i], w1.x, acc[2 * i + 1].x);
        acc[2 * i + 1].y = fmaf(xn[i], w1.y, acc[2 * i + 1].y);
        acc[2 * i + 1].z = fmaf(xn[i], w1.z, acc[2 * i + 1].z);
        acc[2 * i + 1].w = fmaf(xn[i], w1.w, acc[2 * i + 1].w);
    }
}

__global__ void __launch_bounds__(128) k_gemm(int in_sel,
                                              const float* __restrict__ ext,
                                              const float* __restrict__ W,
                                              int relu) {
    __shared__ float4 Ws4[DH * 16];              // 16 KB
    __shared__ float XsT[DH * XT_STRIDE];        // ~34 KB: XsT[k][node], 128 nodes

    const float* xin = (in_sel == 1) ? g_hA : (in_sel == 2) ? g_hB : ext;
    const int tid = threadIdx.x;
    const int r = tid >> 3;      // 0..15 : node group (8 nodes each)
    const int c = tid & 7;       // 0..7  : col group (8 cols each)
    const int node0 = blockIdx.x * 128;

    const float4* W4 = (const float4*)W;
    for (int i = tid; i < DH * 16; i += 128) Ws4[i] = W4[i];

    for (int i = tid; i < 128 * DH; i += 128) {
        int n = i >> 6, k = i & 63;
        int nn = node0 + n;
        float v = (nn < NN) ? xin[nn * DH + k] : 0.0f;
        if (relu) v = fmaxf(v, 0.0f);
        XsT[k * XT_STRIDE + n] = v;
    }
    __syncthreads();

    float4 acc[16];
#pragma unroll
    for (int j = 0; j < 16; j++) acc[j] = make_float4(0.f, 0.f, 0.f, 0.f);

    // prefetch k=0
    float4 xa0 = *(const float4*)&XsT[r * 8];
    float4 xa1 = *(const float4*)&XsT[r * 8 + 4];
    float4 w0  = Ws4[c * 2];
    float4 w1  = Ws4[c * 2 + 1];

#pragma unroll 4
    for (int k = 0; k < DH - 1; k++) {
        // prefetch k+1 BEFORE consuming k -> loads overlap the 64-FMA block
        float4 nxa0 = *(const float4*)&XsT[(k + 1) * XT_STRIDE + r * 8];
        float4 nxa1 = *(const float4*)&XsT[(k + 1) * XT_STRIDE + r * 8 + 4];
        float4 nw0  = Ws4[(k + 1) * 16 + c * 2];
        float4 nw1  = Ws4[(k + 1) * 16 + c * 2 + 1];
        fma8x8(acc, xa0, xa1, w0, w1);
        xa0 = nxa0; xa1 = nxa1; w0 = nw0; w1 = nw1;
    }
    fma8x8(acc, xa0, xa1, w0, w1);   // k = DH-1

#pragma unroll
    for (int i = 0; i < 8; i++) {
        int n = node0 + r * 8 + i;
        if (n < NN) {
            float4* o = (float4*)(g_xw + n * DH + c * 8);
            o[0] = acc[2 * i];
            o[1] = acc[2 * i + 1];
        }
    }
}

// ---------------- pull aggregation: warp per node, 8-deep MLP, no atomics --------
__global__ void __launch_bounds__(256) k_agg(int out_sel, const float* __restrict__ b) {
    int warp = (blockIdx.x * blockDim.x + threadIdx.x) >> 5;
    int lane = threadIdx.x & 31;
    if (warp >= NN) return;
    int n = warp;

    const float2* xw2 = (const float2*)g_xw;
    const float2* b2v = (const float2*)b;

    float di = g_dinv[n];
    float sl = di * di;
    float2 self = xw2[n * 32 + lane];
    float2 bb = b2v[lane];
    float acc0 = fmaf(self.x, sl, bb.x);
    float acc1 = fmaf(self.y, sl, bb.y);

    int beg = g_rowptr[n];
    int end = g_rowptr[n + 1];

    int i = beg;
    for (; i + 8 <= end; i += 8) {
        int2 p0 = g_epack[i];
        int2 p1 = g_epack[i + 1];
        int2 p2 = g_epack[i + 2];
        int2 p3 = g_epack[i + 3];
        int2 p4 = g_epack[i + 4];
        int2 p5 = g_epack[i + 5];
        int2 p6 = g_epack[i + 6];
        int2 p7 = g_epack[i + 7];
        float2 f0 = xw2[p0.x * 32 + lane];
        float2 f1 = xw2[p1.x * 32 + lane];
        float2 f2 = xw2[p2.x * 32 + lane];
        float2 f3 = xw2[p3.x * 32 + lane];
        float2 f4 = xw2[p4.x * 32 + lane];
        float2 f5 = xw2[p5.x * 32 + lane];
        float2 f6 = xw2[p6.x * 32 + lane];
        float2 f7 = xw2[p7.x * 32 + lane];
        acc0 = fmaf(__int_as_float(p0.y), f0.x, acc0);  acc1 = fmaf(__int_as_float(p0.y), f0.y, acc1);
        acc0 = fmaf(__int_as_float(p1.y), f1.x, acc0);  acc1 = fmaf(__int_as_float(p1.y), f1.y, acc1);
        acc0 = fmaf(__int_as_float(p2.y), f2.x, acc0);  acc1 = fmaf(__int_as_float(p2.y), f2.y, acc1);
        acc0 = fmaf(__int_as_float(p3.y), f3.x, acc0);  acc1 = fmaf(__int_as_float(p3.y), f3.y, acc1);
        acc0 = fmaf(__int_as_float(p4.y), f4.x, acc0);  acc1 = fmaf(__int_as_float(p4.y), f4.y, acc1);
        acc0 = fmaf(__int_as_float(p5.y), f5.x, acc0);  acc1 = fmaf(__int_as_float(p5.y), f5.y, acc1);
        acc0 = fmaf(__int_as_float(p6.y), f6.x, acc0);  acc1 = fmaf(__int_as_float(p6.y), f6.y, acc1);
        acc0 = fmaf(__int_as_float(p7.y), f7.x, acc0);  acc1 = fmaf(__int_as_float(p7.y), f7.y, acc1);
    }
    for (; i + 2 <= end; i += 2) {
        int2 p0 = g_epack[i];
        int2 p1 = g_epack[i + 1];
        float2 f0 = xw2[p0.x * 32 + lane];
        float2 f1 = xw2[p1.x * 32 + lane];
        acc0 = fmaf(__int_as_float(p0.y), f0.x, acc0);  acc1 = fmaf(__int_as_float(p0.y), f0.y, acc1);
        acc0 = fmaf(__int_as_float(p1.y), f1.x, acc0);  acc1 = fmaf(__int_as_float(p1.y), f1.y, acc1);
    }
    if (i < end) {
        int2 p = g_epack[i];
        float2 f = xw2[p.x * 32 + lane];
        acc0 = fmaf(__int_as_float(p.y), f.x, acc0);
        acc1 = fmaf(__int_as_float(p.y), f.y, acc1);
    }

    float2* out2 = (float2*)selbuf(out_sel);
    out2[n * 32 + lane] = make_float2(acc0, acc1);
}

// ---------------- fused segmented mean pool + linear head ----------------
__global__ void __launch_bounds__(256) k_pool_head(int h_sel,
                                                   const float* __restrict__ Wl,
                                                   const float* __restrict__ bl,
                                                   float* __restrict__ out) {
    __shared__ float sh[4][DH];
    __shared__ float pooled[DH];
    int g = blockIdx.x;
    int w = threadIdx.x >> 6;
    int c = threadIdx.x & 63;
    int lo = g_gstart[g], hi = g_gstart[g + 1];
    const float* h = selbuf(h_sel);

    float acc = 0.0f;
    for (int n = lo + w; n < hi; n += 4)
        acc += h[n * DH + c];
    sh[w][c] = acc;
    __syncthreads();
    if (w == 0) {
        float s = sh[0][c] + sh[1][c] + sh[2][c] + sh[3][c];
        float cnt = (float)(hi - lo);
        pooled[c] = s / fmaxf(cnt, 1.0f);
    }
    __syncthreads();
    int t = threadIdx.x;
    if (t < NC) {
        float a = bl[t];
#pragma unroll
        for (int hh = 0; hh < DH; hh++) a = fmaf(pooled[hh], Wl[hh * NC + t], a);
        out[g * NC + t] = a;
    }
}

// ---------------- host launch ----------------
extern "C" void kernel_launch(void* const* d_in, const int* in_sizes, int n_in,
                              void* d_out, int out_size) {
    const float* x       = (const float*)d_in[0];
    const int*   ei      = (const int*)d_in[1];   // int32 (JAX x64 disabled)
    const int*   src     = ei;
    const int*   dst     = ei + NE;
    const int*   batch   = (const int*)d_in[2];   // int32, sorted
    const float* ew      = (const float*)d_in[3];
    const float* W1 = (const float*)d_in[4];
    const float* b1 = (const float*)d_in[5];
    const float* W2 = (const float*)d_in[6];
    const float* b2 = (const float*)d_in[7];
    const float* W3 = (const float*)d_in[8];
    const float* b3 = (const float*)d_in[9];
    const float* Wl = (const float*)d_in[10];
    const float* bl = (const float*)d_in[11];
    float* out = (float*)d_out;

    const int TB = 256;
    const int gN   = (NN + TB - 1) / TB;
    const int gE   = (NE + TB - 1) / TB;
    const int gAgg = (NN * 32 + TB - 1) / TB;     // warp per node
    const int gGemm = (NN + 127) / 128;           // 128 nodes per block

    // launches 1-3: start of CSR precompute
    k_init_deg<<<gN, TB>>>();
    k_deg_hist<<<gE, TB>>>(dst, ew);
    k_scan_local<<<SCAN_NB, SCAN_BS>>>();
    // launch 4: gemm layer 1 (independent of CSR chain) -- profiled by ncu
    k_gemm<<<gGemm, 128>>>(0, x, W1, 0);
    // finish CSR precompute
    k_scan_block<<<1, 128>>>();
    k_scan_add_rsqrt<<<gN, TB>>>(batch);
    k_scatter<<<gE, TB>>>(src, dst, ew);

    // layer 1 aggregation -> hA   (relu deferred to layer 2 read)
    k_agg<<<gAgg, TB>>>(1, b1);

    // layer 2: relu(hA) @ W2 -> agg -> hB
    k_gemm<<<gGemm, 128>>>(1, nullptr, W2, 1);
    k_agg<<<gAgg, TB>>>(2, b2);

    // layer 3: relu(hB) @ W3 -> agg -> hA (= h3, no relu)
    k_gemm<<<gGemm, 128>>>(2, nullptr, W3, 1);
    k_agg<<<gAgg, TB>>>(1, b3);

    // fused global mean pool + linear head
    k_pool_head<<<NG, TB>>>(1, Wl, bl, out);
}

// round 12
// speedup vs baseline: 1.0822x; 1.0417x over previous
#include <cuda_runtime.h>
#include <cuda_bf16.h>
#include <cstdint>

#define NN 50000
#define NE 800000
#define DH 64
#define NG 128
#define NC 10

#define SCAN_BS 512
#define SCAN_NB ((NN + SCAN_BS - 1) / SCAN_BS)   // 98

// smem layout for mma gemm (bf16 tiles, 72-bf16 row stride -> conflict-free frags)
#define XROW 72
#define XH_OFF 0                         // 128*72*2 = 18432
#define XL_OFF 18432
#define WH_OFF (18432 * 2)               // 64*72*2 = 9216
#define WL_OFF (18432 * 2 + 9216)
#define GEMM_SMEM (18432 * 2 + 9216 * 2) // 55296 B

// ---------------- scratch (static device globals; no allocation) ----------------
__device__ __align__(16) float g_dinv[NN];
__device__ int   g_rowcnt[NN];
__device__ int   g_rowptr[NN + 1];
__device__ int   g_cursor[NN];
__device__ int   g_bsum[SCAN_NB];
__device__ int   g_gstart[NG + 1];
__device__ __align__(16) int2  g_epack[NE];         // {src, norm-as-int} sorted by dst
__device__ __align__(16) float g_xw[NN * DH];
__device__ __align__(16) float g_hA[NN * DH];
__device__ __align__(16) float g_hB[NN * DH];

__device__ __forceinline__ float* selbuf(int s) {
    return (s == 1) ? g_hA : g_hB;
}

// ---------------- degree precompute ----------------
__global__ void k_init_deg() {
    int n = blockIdx.x * blockDim.x + threadIdx.x;
    if (n < NN) { g_dinv[n] = 1.0f; g_rowcnt[n] = 0; }
}

__global__ void k_deg_hist(const int* __restrict__ dst,
                           const float* __restrict__ ew) {
    int e = blockIdx.x * blockDim.x + threadIdx.x;
    if (e < NE) {
        int d = dst[e];
        atomicAdd(&g_dinv[d], ew[e]);
        atomicAdd(&g_rowcnt[d], 1);
    }
}

// ---------------- 3-phase parallel exclusive scan of rowcnt ----------------
__global__ void __launch_bounds__(SCAN_BS) k_scan_local() {
    __shared__ int sh[SCAN_BS];
    int t = threadIdx.x;
    int idx = blockIdx.x * SCAN_BS + t;
    int val = (idx < NN) ? g_rowcnt[idx] : 0;
    sh[t] = val;
    __syncthreads();
#pragma unroll
    for (int off = 1; off < SCAN_BS; off <<= 1) {
        int v = sh[t];
        if (t >= off) v += sh[t - off];
        __syncthreads();
        sh[t] = v;
        __syncthreads();
    }
    if (idx < NN) g_rowptr[idx] = sh[t] - val;
    if (t == SCAN_BS - 1) g_bsum[blockIdx.x] = sh[t];
}

__global__ void __launch_bounds__(128) k_scan_block() {
    __shared__ int sh[128];
    int t = threadIdx.x;
    int val = (t < SCAN_NB) ? g_bsum[t] : 0;
    sh[t] = val;
    __syncthreads();
#pragma unroll
    for (int off = 1; off < 128; off <<= 1) {
        int v = sh[t];
        if (t >= off) v += sh[t - off];
        __syncthreads();
        sh[t] = v;
        __syncthreads();
    }
    if (t < SCAN_NB) g_bsum[t] = sh[t] - val;
}

__global__ void k_scan_add_rsqrt(const int* __restrict__ batch) {
    int idx = blockIdx.x * blockDim.x + threadIdx.x;
    if (idx < NN) {
        int v = g_rowptr[idx] + g_bsum[idx / SCAN_BS];
        g_rowptr[idx] = v;
        g_cursor[idx] = v;
        float d = g_dinv[idx];
        g_dinv[idx] = (d > 0.0f) ? rsqrtf(d) : 0.0f;

        int b0 = batch[idx];
        int b1 = (idx + 1 < NN) ? batch[idx + 1] : NG;
        for (int g = b0 + 1; g <= b1; g++) g_gstart[g] = idx + 1;
        if (idx == 0) {
            for (int g = 0; g <= b0; g++) g_gstart[g] = 0;
        }
    }
    if (idx == 0) g_rowptr[NN] = NE;
}

__global__ void k_scatter(const int* __restrict__ src,
                          const int* __restrict__ dst,
                          const float* __restrict__ ew) {
    int e = blockIdx.x * blockDim.x + threadIdx.x;
    if (e < NE) {
        int s = src[e], d = dst[e];
        int pos = atomicAdd(&g_cursor[d], 1);
        float nm = g_dinv[s] * ew[e] * g_dinv[d];
        g_epack[pos] = make_int2(s, __float_as_int(nm));
    }
}

// ---------------- bf16 helpers ----------------
__device__ __forceinline__ uint32_t pack_hi(float a, float b) {
    __nv_bfloat162 h;
    h.x = __float2bfloat16(a);
    h.y = __float2bfloat16(b);
    return *(uint32_t*)&h;
}
__device__ __forceinline__ uint32_t pack_lo(float a, float b) {
    float ra = a - __bfloat162float(__float2bfloat16(a));
    float rb = b - __bfloat162float(__float2bfloat16(b));
    __nv_bfloat162 l;
    l.x = __float2bfloat16(ra);
    l.y = __float2bfloat16(rb);
    return *(uint32_t*)&l;
}

__device__ __forceinline__ void mma16816(float& c0, float& c1, float& c2, float& c3,
                                         uint32_t a0, uint32_t a1, uint32_t a2, uint32_t a3,
                                         uint32_t b0, uint32_t b1) {
    asm volatile(
        "mma.sync.aligned.m16n8k16.row.col.f32.bf16.bf16.f32 "
        "{%0,%1,%2,%3}, {%4,%5,%6,%7}, {%8,%9}, {%0,%1,%2,%3};"
        : "+f"(c0), "+f"(c1), "+f"(c2), "+f"(c3)
        : "r"(a0), "r"(a1), "r"(a2), "r"(a3), "r"(b0), "r"(b1));
}

// ---------------- tensor-core GEMM via mma.sync bf16 3-term split ----------------
// xw[node0..node0+128) = relu?(xin) @ W.  D = Xh@Wh + Xh@Wl + Xl@Wh (fp32 accum).
// Block: 256 thr = 8 warps; warp w owns rows [w*16, w*16+16), all 64 cols.
__global__ void __launch_bounds__(256) k_gemm(int in_sel,
                                              const float* __restrict__ ext,
                                              const float* __restrict__ W,
                                              int relu) {
    extern __shared__ char smem[];
    const float* xin = (in_sel == 1) ? g_hA : (in_sel == 2) ? g_hB : ext;
    const int tid = threadIdx.x;
    const int node0 = blockIdx.x * 128;

    // stage X as bf16 hi/lo (relu fused). thread handles one (m, k-pair).
    for (int i = tid; i < 128 * 32; i += 256) {
        int m = i >> 5, kp = i & 31;
        int n = node0 + m;
        float2 v = make_float2(0.f, 0.f);
        if (n < NN) v = *(const float2*)&xin[n * DH + 2 * kp];
        if (relu) { v.x = fmaxf(v.x, 0.f); v.y = fmaxf(v.y, 0.f); }
        uint32_t off = (uint32_t)(m * XROW + 2 * kp) * 2;
        *(uint32_t*)(smem + XH_OFF + off) = pack_hi(v.x, v.y);
        *(uint32_t*)(smem + XL_OFF + off) = pack_lo(v.x, v.y);
    }
    // stage WT[n][k] = W[k][n] as bf16 hi/lo, k-pairs packed.
    for (int i = tid; i < 64 * 32; i += 256) {
        int n = i & 63, kp = i >> 6;
        float w0 = W[(2 * kp) * DH + n];
        float w1 = W[(2 * kp + 1) * DH + n];
        uint32_t off = (uint32_t)(n * XROW + 2 * kp) * 2;
        *(uint32_t*)(smem + WH_OFF + off) = pack_hi(w0, w1);
        *(uint32_t*)(smem + WL_OFF + off) = pack_lo(w0, w1);
    }
    __syncthreads();

    const int lane = tid & 31;
    const int wid = tid >> 5;
    const int g = lane >> 2;      // group 0..7
    const int t = lane & 3;       // thread-in-group
    const int m0 = wid * 16;

    float acc[8][4];
#pragma unroll
    for (int j = 0; j < 8; j++)
#pragma unroll
        for (int q = 0; q < 4; q++) acc[j][q] = 0.f;

    const int xoffs[3] = {XH_OFF, XH_OFF, XL_OFF};
    const int woffs[3] = {WH_OFF, WL_OFF, WH_OFF};

#pragma unroll
    for (int term = 0; term < 3; term++) {
        const char* xb = smem + xoffs[term];
        const char* wb = smem + woffs[term];
#pragma unroll
        for (int kc = 0; kc < 4; kc++) {
            int k0 = kc * 16;
            // A fragment (m16 x k16, row-major): PTX ISA layout
            uint32_t a0 = *(const uint32_t*)(xb + ((m0 + g) * XROW + k0 + 2 * t) * 2);
            uint32_t a1 = *(const uint32_t*)(xb + ((m0 + g + 8) * XROW + k0 + 2 * t) * 2);
            uint32_t a2 = *(const uint32_t*)(xb + ((m0 + g) * XROW + k0 + 2 * t + 8) * 2);
            uint32_t a3 = *(const uint32_t*)(xb + ((m0 + g + 8) * XROW + k0 + 2 * t + 8) * 2);
#pragma unroll
            for (int j = 0; j < 8; j++) {
                int n0 = j * 8;
                uint32_t b0 = *(const uint32_t*)(wb + ((n0 + g) * XROW + k0 + 2 * t) * 2);
                uint32_t b1 = *(const uint32_t*)(wb + ((n0 + g) * XROW + k0 + 2 * t + 8) * 2);
                mma16816(acc[j][0], acc[j][1], acc[j][2], acc[j][3],
                         a0, a1, a2, a3, b0, b1);
            }
        }
    }

    // store: C layout rows g / g+8, cols 2t / 2t+1 within each n-tile
    int row0 = node0 + m0 + g;
    int row1 = row0 + 8;
#pragma unroll
    for (int j = 0; j < 8; j++) {
        int col = j * 8 + 2 * t;
        if (row0 < NN) *(float2*)&g_xw[row0 * DH + col] = make_float2(acc[j][0], acc[j][1]);
        if (row1 < NN) *(float2*)&g_xw[row1 * DH + col] = make_float2(acc[j][2], acc[j][3]);
    }
}

// ---------------- pull aggregation: warp per node, 8-deep MLP, no atomics --------
__global__ void __launch_bounds__(256) k_agg(int out_sel, const float* __restrict__ b) {
    int warp = (blockIdx.x * blockDim.x + threadIdx.x) >> 5;
    int lane = threadIdx.x & 31;
    if (warp >= NN) return;
    int n = warp;

    const float2* xw2 = (const float2*)g_xw;
    const float2* b2v = (const float2*)b;

    float di = g_dinv[n];
    float sl = di * di;
    float2 self = xw2[n * 32 + lane];
    float2 bb = b2v[lane];
    float acc0 = fmaf(self.x, sl, bb.x);
    float acc1 = fmaf(self.y, sl, bb.y);

    int beg = g_rowptr[n];
    int end = g_rowptr[n + 1];

    int i = beg;
    for (; i + 8 <= end; i += 8) {
        int2 p0 = g_epack[i];
        int2 p1 = g_epack[i + 1];
        int2 p2 = g_epack[i + 2];
        int2 p3 = g_epack[i + 3];
        int2 p4 = g_epack[i + 4];
        int2 p5 = g_epack[i + 5];
        int2 p6 = g_epack[i + 6];
        int2 p7 = g_epack[i + 7];
        float2 f0 = xw2[p0.x * 32 + lane];
        float2 f1 = xw2[p1.x * 32 + lane];
        float2 f2 = xw2[p2.x * 32 + lane];
        float2 f3 = xw2[p3.x * 32 + lane];
        float2 f4 = xw2[p4.x * 32 + lane];
        float2 f5 = xw2[p5.x * 32 + lane];
        float2 f6 = xw2[p6.x * 32 + lane];
        float2 f7 = xw2[p7.x * 32 + lane];
        acc0 = fmaf(__int_as_float(p0.y), f0.x, acc0);  acc1 = fmaf(__int_as_float(p0.y), f0.y, acc1);
        acc0 = fmaf(__int_as_float(p1.y), f1.x, acc0);  acc1 = fmaf(__int_as_float(p1.y), f1.y, acc1);
        acc0 = fmaf(__int_as_float(p2.y), f2.x, acc0);  acc1 = fmaf(__int_as_float(p2.y), f2.y, acc1);
        acc0 = fmaf(__int_as_float(p3.y), f3.x, acc0);  acc1 = fmaf(__int_as_float(p3.y), f3.y, acc1);
        acc0 = fmaf(__int_as_float(p4.y), f4.x, acc0);  acc1 = fmaf(__int_as_float(p4.y), f4.y, acc1);
        acc0 = fmaf(__int_as_float(p5.y), f5.x, acc0);  acc1 = fmaf(__int_as_float(p5.y), f5.y, acc1);
        acc0 = fmaf(__int_as_float(p6.y), f6.x, acc0);  acc1 = fmaf(__int_as_float(p6.y), f6.y, acc1);
        acc0 = fmaf(__int_as_float(p7.y), f7.x, acc0);  acc1 = fmaf(__int_as_float(p7.y), f7.y, acc1);
    }
    for (; i + 2 <= end; i += 2) {
        int2 p0 = g_epack[i];
        int2 p1 = g_epack[i + 1];
        float2 f0 = xw2[p0.x * 32 + lane];
        float2 f1 = xw2[p1.x * 32 + lane];
        acc0 = fmaf(__int_as_float(p0.y), f0.x, acc0);  acc1 = fmaf(__int_as_float(p0.y), f0.y, acc1);
        acc0 = fmaf(__int_as_float(p1.y), f1.x, acc0);  acc1 = fmaf(__int_as_float(p1.y), f1.y, acc1);
    }
    if (i < end) {
        int2 p = g_epack[i];
        float2 f = xw2[p.x * 32 + lane];
        acc0 = fmaf(__int_as_float(p.y), f.x, acc0);
        acc1 = fmaf(__int_as_float(p.y), f.y, acc1);
    }

    float2* out2 = (float2*)selbuf(out_sel);
    out2[n * 32 + lane] = make_float2(acc0, acc1);
}

// ---------------- fused segmented mean pool + linear head ----------------
__global__ void __launch_bounds__(256) k_pool_head(int h_sel,
                                                   const float* __restrict__ Wl,
                                                   const float* __restrict__ bl,
                                                   float* __restrict__ out) {
    __shared__ float sh[4][DH];
    __shared__ float pooled[DH];
    int g = blockIdx.x;
    int w = threadIdx.x >> 6;
    int c = threadIdx.x & 63;
    int lo = g_gstart[g], hi = g_gstart[g + 1];
    const float* h = selbuf(h_sel);

    float acc = 0.0f;
    for (int n = lo + w; n < hi; n += 4)
        acc += h[n * DH + c];
    sh[w][c] = acc;
    __syncthreads();
    if (w == 0) {
        float s = sh[0][c] + sh[1][c] + sh[2][c] + sh[3][c];
        float cnt = (float)(hi - lo);
        pooled[c] = s / fmaxf(cnt, 1.0f);
    }
    __syncthreads();
    int t = threadIdx.x;
    if (t < NC) {
        float a = bl[t];
#pragma unroll
        for (int hh = 0; hh < DH; hh++) a = fmaf(pooled[hh], Wl[hh * NC + t], a);
        out[g * NC + t] = a;
    }
}

// ---------------- host launch ----------------
extern "C" void kernel_launch(void* const* d_in, const int* in_sizes, int n_in,
                              void* d_out, int out_size) {
    const float* x       = (const float*)d_in[0];
    const int*   ei      = (const int*)d_in[1];   // int32 (JAX x64 disabled)
    const int*   src     = ei;
    const int*   dst     = ei + NE;
    const int*   batch   = (const int*)d_in[2];   // int32, sorted
    const float* ew      = (const float*)d_in[3];
    const float* W1 = (const float*)d_in[4];
    const float* b1 = (const float*)d_in[5];
    const float* W2 = (const float*)d_in[6];
    const float* b2 = (const float*)d_in[7];
    const float* W3 = (const float*)d_in[8];
    const float* b3 = (const float*)d_in[9];
    const float* Wl = (const float*)d_in[10];
    const float* bl = (const float*)d_in[11];
    float* out = (float*)d_out;

    static bool attr_set = false;
    if (!attr_set) {
        cudaFuncSetAttribute(k_gemm, cudaFuncAttributeMaxDynamicSharedMemorySize, GEMM_SMEM);
        attr_set = true;
    }

    const int TB = 256;
    const int gN   = (NN + TB - 1) / TB;
    const int gE   = (NE + TB - 1) / TB;
    const int gAgg = (NN * 32 + TB - 1) / TB;     // warp per node
    const int gGemm = (NN + 127) / 128;           // 128 nodes per block

    // launches 1-3: start of CSR precompute
    k_init_deg<<<gN, TB>>>();
    k_deg_hist<<<gE, TB>>>(dst, ew);
    k_scan_local<<<SCAN_NB, SCAN_BS>>>();
    // launch 4: gemm layer 1 (independent of CSR chain) -- profiled by ncu
    k_gemm<<<gGemm, 256, GEMM_SMEM>>>(0, x, W1, 0);
    // finish CSR precompute
    k_scan_block<<<1, 128>>>();
    k_scan_add_rsqrt<<<gN, TB>>>(batch);
    k_scatter<<<gE, TB>>>(src, dst, ew);

    // layer 1 aggregation -> hA   (relu deferred to layer 2 read)
    k_agg<<<gAgg, TB>>>(1, b1);

    // layer 2: relu(hA) @ W2 -> agg -> hB
    k_gemm<<<gGemm, 256, GEMM_SMEM>>>(1, nullptr, W2, 1);
    k_agg<<<gAgg, TB>>>(2, b2);

    // layer 3: relu(hB) @ W3 -> agg -> hA (= h3, no relu)
    k_gemm<<<gGemm, 256, GEMM_SMEM>>>(2, nullptr, W3, 1);
    k_agg<<<gAgg, TB>>>(1, b3);

    // fused global mean pool + linear head
    k_pool_head<<<NG, TB>>>(1, Wl, bl, out);
}